// round 7
// baseline (speedup 1.0000x reference)
#include <cuda_runtime.h>
#include <math.h>

#define BB 2
#define NN 8192
#define KK 32
#define CC 128
#define HH 128
#define ALPHA 0.3f
#define EPS 1e-6f

#define RT 64                    // rows per block tile
#define BST 130                  // Bs_T stride (floats): 130%32==2 -> conflict-free LDS.64
#define AS_FLOATS (RT * CC)      // 8192
#define BS_FLOATS (HH * BST)     // 16640
#define SMEM_BYTES ((AS_FLOATS + BS_FLOATS) * 4)   // 99328 B

typedef unsigned long long ull;

__device__ float g_H[(size_t)BB * NN * HH];    // leaky(emb @ Qw + Qb), 8 MB
__device__ float g_wsh[(size_t)BB * NN * HH];  // weighted-sum hidden,  8 MB

__device__ __forceinline__ void ffma2(ull& acc, ull a, ull b) {
    asm("fma.rn.f32x2 %0, %1, %2, %0;" : "+l"(acc) : "l"(a), "l"(b));
}
__device__ __forceinline__ void unpack2(ull v, float& lo, float& hi) {
    asm("mov.b64 {%0, %1}, %2;" : "=f"(lo), "=f"(hi) : "l"(v));
}
__device__ __forceinline__ float leaky(float v) {
    return (v >= 0.f) ? v : ALPHA * v;
}

// ---- stage A: 64 rows x 128 cols, row-major direct copy (no transpose) ----
__device__ __forceinline__ void stage_A(float* __restrict__ As,
                                        const float* __restrict__ src, int t) {
    const float4* s4 = (const float4*)src;
    float4* d4 = (float4*)As;
#pragma unroll
    for (int i = 0; i < 8; i++) d4[t + i * 256] = s4[t + i * 256];
}

// ---- stage B transposed: W[128k][128h] -> Bs_T[h][k] (stride BST) ---------
// 4x4 tiles; reads coalesced LDG.128, writes STS.64 of (k,k+1) pairs.
__device__ __forceinline__ void stage_BT(float* __restrict__ Bs,
                                         const float* __restrict__ W, int t) {
#pragma unroll
    for (int it = 0; it < 4; it++) {
        int id = t + it * 256;
        int k0 = (id >> 5) * 4;
        int h0 = (id & 31) * 4;
        float4 r0 = *(const float4*)(W + (k0 + 0) * HH + h0);
        float4 r1 = *(const float4*)(W + (k0 + 1) * HH + h0);
        float4 r2 = *(const float4*)(W + (k0 + 2) * HH + h0);
        float4 r3 = *(const float4*)(W + (k0 + 3) * HH + h0);
        *(float2*)(Bs + (h0 + 0) * BST + k0)     = make_float2(r0.x, r1.x);
        *(float2*)(Bs + (h0 + 0) * BST + k0 + 2) = make_float2(r2.x, r3.x);
        *(float2*)(Bs + (h0 + 1) * BST + k0)     = make_float2(r0.y, r1.y);
        *(float2*)(Bs + (h0 + 1) * BST + k0 + 2) = make_float2(r2.y, r3.y);
        *(float2*)(Bs + (h0 + 2) * BST + k0)     = make_float2(r0.z, r1.z);
        *(float2*)(Bs + (h0 + 2) * BST + k0 + 2) = make_float2(r2.z, r3.z);
        *(float2*)(Bs + (h0 + 3) * BST + k0)     = make_float2(r0.w, r1.w);
        *(float2*)(Bs + (h0 + 3) * BST + k0 + 2) = make_float2(r2.w, r3.w);
    }
}

// ---- mainloop over K=128: acc[r][j] f32x2 lanes = (even-k, odd-k) sums ----
// thread (tr=t>>5, tc=t&31): rows tr*8..+7, cols tc+32j. A broadcast, B cf.
__device__ __forceinline__ void gemm_128(const float* __restrict__ As,
                                         const float* __restrict__ Bs,
                                         int tr, int tc, ull acc[8][4]) {
    const float* Ar = As + tr * 8 * CC;
    const float* Bc = Bs + tc * BST;
#pragma unroll 4
    for (int kp = 0; kp < 64; kp++) {
        const int k2 = 2 * kp;
        ull b0 = *(const ull*)(Bc + 0 * 32 * BST + k2);
        ull b1 = *(const ull*)(Bc + 1 * 32 * BST + k2);
        ull b2 = *(const ull*)(Bc + 2 * 32 * BST + k2);
        ull b3 = *(const ull*)(Bc + 3 * 32 * BST + k2);
#pragma unroll
        for (int r = 0; r < 8; r++) {
            ull a = *(const ull*)(Ar + r * CC + k2);
            ffma2(acc[r][0], a, b0);
            ffma2(acc[r][1], a, b1);
            ffma2(acc[r][2], a, b2);
            ffma2(acc[r][3], a, b3);
        }
    }
}

// ---------------------------------------------------------------------------
// K1: H[row,h] = leaky(emb[row,:] @ Qw + Qb)
// ---------------------------------------------------------------------------
__global__ void __launch_bounds__(256) k1_qgemm(const float* __restrict__ emb,
                                                const float* __restrict__ Qw,
                                                const float* __restrict__ Qb) {
    extern __shared__ float sm[];
    float* As = sm;
    float* Bs = sm + AS_FLOATS;
    const int t = threadIdx.x;
    const int tr = t >> 5, tc = t & 31;
    const int row0 = blockIdx.x * RT;

    stage_A(As, emb + (size_t)row0 * CC, t);
    stage_BT(Bs, Qw, t);
    __syncthreads();

    ull acc[8][4];
#pragma unroll
    for (int r = 0; r < 8; r++)
#pragma unroll
        for (int j = 0; j < 4; j++) acc[r][j] = 0ull;

    gemm_128(As, Bs, tr, tc, acc);

    float bias[4];
#pragma unroll
    for (int j = 0; j < 4; j++) bias[j] = Qb[tc + 32 * j];

    const int rbase = row0 + tr * 8;
#pragma unroll
    for (int r = 0; r < 8; r++) {
        float* o = g_H + (size_t)(rbase + r) * HH + tc;
#pragma unroll
        for (int j = 0; j < 4; j++) {
            float lo, hi;
            unpack2(acc[r][j], lo, hi);
            o[32 * j] = leaky(lo + hi + bias[j]);
        }
    }
}

// ---------------------------------------------------------------------------
// K2: wsh[b,n,h] = sum_k H[b,js[k],h]*ws[k] / (sum_k ws + eps)
// ---------------------------------------------------------------------------
__global__ void __launch_bounds__(128) k2_gather(const float* __restrict__ weights,
                                                 const int* __restrict__ ns) {
    const int n = blockIdx.x;
    const int t = threadIdx.x;
    const int c4 = t & 31;
    const int kg = t >> 5;

    __shared__ float ws[KK];
    __shared__ int   js[KK];
    __shared__ float wsum_s;
    __shared__ float4 red0[4][32];
    __shared__ float4 red1[4][32];

    if (t < KK) {
        int j = ns[n * KK + t];
        js[t] = j;
        float w = weights[(size_t)n * NN + j];
        ws[t] = w;
#pragma unroll
        for (int off = 16; off; off >>= 1)
            w += __shfl_xor_sync(0xffffffffu, w, off);
        if (t == 0) wsum_s = w;
    }
    __syncthreads();

    const float* H0 = g_H;
    const float* H1 = g_H + (size_t)NN * HH;
    float4 a0 = make_float4(0.f, 0.f, 0.f, 0.f);
    float4 a1 = make_float4(0.f, 0.f, 0.f, 0.f);
#pragma unroll
    for (int k = kg; k < KK; k += 4) {
        const int j = js[k];
        const float w = ws[k];
        const float4 h0 = *(const float4*)&H0[(size_t)j * HH + 4 * c4];
        const float4 h1 = *(const float4*)&H1[(size_t)j * HH + 4 * c4];
        a0.x = fmaf(h0.x, w, a0.x); a0.y = fmaf(h0.y, w, a0.y);
        a0.z = fmaf(h0.z, w, a0.z); a0.w = fmaf(h0.w, w, a0.w);
        a1.x = fmaf(h1.x, w, a1.x); a1.y = fmaf(h1.y, w, a1.y);
        a1.z = fmaf(h1.z, w, a1.z); a1.w = fmaf(h1.w, w, a1.w);
    }
    red0[kg][c4] = a0;
    red1[kg][c4] = a1;
    __syncthreads();

    if (t < 64) {
        const int b = t >> 5;
        const int c = t & 31;
        const float4 p0 = b ? red1[0][c] : red0[0][c];
        const float4 p1 = b ? red1[1][c] : red0[1][c];
        const float4 p2 = b ? red1[2][c] : red0[2][c];
        const float4 p3 = b ? red1[3][c] : red0[3][c];
        const float inv = 1.f / (wsum_s + EPS);
        float4 o;
        o.x = (p0.x + p1.x + p2.x + p3.x) * inv;
        o.y = (p0.y + p1.y + p2.y + p3.y) * inv;
        o.z = (p0.z + p1.z + p2.z + p3.z) * inv;
        o.w = (p0.w + p1.w + p2.w + p3.w) * inv;
        *(float4*)&g_wsh[((size_t)b * NN + n) * HH + 4 * c] = o;
    }
}

// ---------------------------------------------------------------------------
// K3: out = normalize(leaky([emb | wsh] @ Ww + Wb)), two K=128 stages
// ---------------------------------------------------------------------------
__global__ void __launch_bounds__(256) k3_out(const float* __restrict__ emb,
                                              const float* __restrict__ Ww,
                                              const float* __restrict__ Wb,
                                              float* __restrict__ out) {
    extern __shared__ float sm[];
    float* As = sm;
    float* Bs = sm + AS_FLOATS;
    const int t = threadIdx.x;
    const int tr = t >> 5, tc = t & 31;
    const int row0 = blockIdx.x * RT;

    ull acc[8][4];
#pragma unroll
    for (int r = 0; r < 8; r++)
#pragma unroll
        for (int j = 0; j < 4; j++) acc[r][j] = 0ull;

    // stage 0: A = emb rows, B = Ww[0:128,:]
    stage_A(As, emb + (size_t)row0 * CC, t);
    stage_BT(Bs, Ww, t);
    __syncthreads();
    gemm_128(As, Bs, tr, tc, acc);
    __syncthreads();

    // stage 1: A = wsh rows, B = Ww[128:256,:]
    stage_A(As, g_wsh + (size_t)row0 * HH, t);
    stage_BT(Bs, Ww + 128 * HH, t);
    __syncthreads();
    gemm_128(As, Bs, tr, tc, acc);

    float bias[4];
#pragma unroll
    for (int j = 0; j < 4; j++) bias[j] = Wb[tc + 32 * j];

    float v[8][4];
#pragma unroll
    for (int r = 0; r < 8; r++) {
        float s = 0.f;
#pragma unroll
        for (int j = 0; j < 4; j++) {
            float lo, hi;
            unpack2(acc[r][j], lo, hi);
            float x = leaky(lo + hi + bias[j]);
            v[r][j] = x;
            s = fmaf(x, x, s);
        }
        // full-warp reduce: warp covers all 32 tc for this tr -> row sum-sq
#pragma unroll
        for (int off = 16; off; off >>= 1)
            s += __shfl_xor_sync(0xffffffffu, s, off);
        const float inv = 1.f / (sqrtf(s) + EPS);
        float* o = out + (size_t)(row0 + tr * 8 + r) * HH + tc;
#pragma unroll
        for (int j = 0; j < 4; j++) o[32 * j] = v[r][j] * inv;
    }
}

// ---------------------------------------------------------------------------
extern "C" void kernel_launch(void* const* d_in, const int* in_sizes, int n_in,
                              void* d_out, int out_size) {
    const float* emb     = (const float*)d_in[0];  // (B, N, C)
    const float* weights = (const float*)d_in[1];  // (N, N)
    const int*   ns      = (const int*)  d_in[2];  // (N, K)
    const float* Qw      = (const float*)d_in[3];  // (C, H)
    const float* Qb      = (const float*)d_in[4];  // (H,)
    const float* Ww      = (const float*)d_in[5];  // (C+H, H)
    const float* Wb      = (const float*)d_in[6];  // (H,)
    float* out = (float*)d_out;                    // (B, N, H)

    (void)in_sizes; (void)n_in; (void)out_size;

    cudaFuncSetAttribute(k1_qgemm, cudaFuncAttributeMaxDynamicSharedMemorySize,
                         SMEM_BYTES);
    cudaFuncSetAttribute(k3_out, cudaFuncAttributeMaxDynamicSharedMemorySize,
                         SMEM_BYTES);

    k1_qgemm<<<(BB * NN) / RT, 256, SMEM_BYTES>>>(emb, Qw, Qb);
    k2_gather<<<NN, 128>>>(weights, ns);
    k3_out<<<(BB * NN) / RT, 256, SMEM_BYTES>>>(emb, Ww, Wb, out);
}

// round 9
// speedup vs baseline: 1.0008x; 1.0008x over previous
#include <cuda_runtime.h>
#include <math.h>

#define BB 2
#define NN 8192
#define KK 32
#define CC 128
#define HH 128
#define ALPHA 0.3f
#define EPS 1e-6f

#define RT 64                    // rows per block tile
#define BST 130                  // Bs_T stride (floats): 130%32==2 -> conflict-free LDS.64
#define AS_FLOATS (RT * CC)      // 8192
#define BS_FLOATS (HH * BST)     // 16640
#define SMEM_BYTES ((AS_FLOATS + BS_FLOATS) * 4)   // 99328 B

typedef unsigned long long ull;

__device__ float g_H[(size_t)BB * NN * HH];    // leaky(emb @ Qw + Qb), 8 MB
__device__ float g_wsh[(size_t)BB * NN * HH];  // weighted-sum hidden,  8 MB

__device__ __forceinline__ void ffma2(ull& acc, ull a, ull b) {
    asm("fma.rn.f32x2 %0, %1, %2, %0;" : "+l"(acc) : "l"(a), "l"(b));
}
__device__ __forceinline__ void unpack2(ull v, float& lo, float& hi) {
    asm("mov.b64 {%0, %1}, %2;" : "=f"(lo), "=f"(hi) : "l"(v));
}
__device__ __forceinline__ float leaky(float v) {
    return (v >= 0.f) ? v : ALPHA * v;
}

// ---- stage A: 64 rows x 128 cols, row-major direct copy (no transpose) ----
__device__ __forceinline__ void stage_A(float* __restrict__ As,
                                        const float* __restrict__ src, int t) {
    const float4* s4 = (const float4*)src;
    float4* d4 = (float4*)As;
#pragma unroll
    for (int i = 0; i < 8; i++) d4[t + i * 256] = s4[t + i * 256];
}

// ---- stage B transposed: W[128k][128h] -> Bs_T[h][k] (stride BST) ---------
// 4x4 tiles; reads coalesced LDG.128, writes STS.64 of (k,k+1) pairs.
__device__ __forceinline__ void stage_BT(float* __restrict__ Bs,
                                         const float* __restrict__ W, int t) {
#pragma unroll
    for (int it = 0; it < 4; it++) {
        int id = t + it * 256;
        int k0 = (id >> 5) * 4;
        int h0 = (id & 31) * 4;
        float4 r0 = *(const float4*)(W + (k0 + 0) * HH + h0);
        float4 r1 = *(const float4*)(W + (k0 + 1) * HH + h0);
        float4 r2 = *(const float4*)(W + (k0 + 2) * HH + h0);
        float4 r3 = *(const float4*)(W + (k0 + 3) * HH + h0);
        *(float2*)(Bs + (h0 + 0) * BST + k0)     = make_float2(r0.x, r1.x);
        *(float2*)(Bs + (h0 + 0) * BST + k0 + 2) = make_float2(r2.x, r3.x);
        *(float2*)(Bs + (h0 + 1) * BST + k0)     = make_float2(r0.y, r1.y);
        *(float2*)(Bs + (h0 + 1) * BST + k0 + 2) = make_float2(r2.y, r3.y);
        *(float2*)(Bs + (h0 + 2) * BST + k0)     = make_float2(r0.z, r1.z);
        *(float2*)(Bs + (h0 + 2) * BST + k0 + 2) = make_float2(r2.z, r3.z);
        *(float2*)(Bs + (h0 + 3) * BST + k0)     = make_float2(r0.w, r1.w);
        *(float2*)(Bs + (h0 + 3) * BST + k0 + 2) = make_float2(r2.w, r3.w);
    }
}

// ---- mainloop over K=128: acc[r][j] f32x2 lanes = (even-k, odd-k) sums ----
// thread (tr=t>>5, tc=t&31): rows tr*8..+7, cols tc+32j. A broadcast, B cf.
__device__ __forceinline__ void gemm_128(const float* __restrict__ As,
                                         const float* __restrict__ Bs,
                                         int tr, int tc, ull acc[8][4]) {
    const float* Ar = As + tr * 8 * CC;
    const float* Bc = Bs + tc * BST;
#pragma unroll 4
    for (int kp = 0; kp < 64; kp++) {
        const int k2 = 2 * kp;
        ull b0 = *(const ull*)(Bc + 0 * 32 * BST + k2);
        ull b1 = *(const ull*)(Bc + 1 * 32 * BST + k2);
        ull b2 = *(const ull*)(Bc + 2 * 32 * BST + k2);
        ull b3 = *(const ull*)(Bc + 3 * 32 * BST + k2);
#pragma unroll
        for (int r = 0; r < 8; r++) {
            ull a = *(const ull*)(Ar + r * CC + k2);
            ffma2(acc[r][0], a, b0);
            ffma2(acc[r][1], a, b1);
            ffma2(acc[r][2], a, b2);
            ffma2(acc[r][3], a, b3);
        }
    }
}

// ---------------------------------------------------------------------------
// K1: H[row,h] = leaky(emb[row,:] @ Qw + Qb)
// ---------------------------------------------------------------------------
__global__ void __launch_bounds__(256) k1_qgemm(const float* __restrict__ emb,
                                                const float* __restrict__ Qw,
                                                const float* __restrict__ Qb) {
    extern __shared__ float sm[];
    float* As = sm;
    float* Bs = sm + AS_FLOATS;
    const int t = threadIdx.x;
    const int tr = t >> 5, tc = t & 31;
    const int row0 = blockIdx.x * RT;

    stage_A(As, emb + (size_t)row0 * CC, t);
    stage_BT(Bs, Qw, t);
    __syncthreads();

    ull acc[8][4];
#pragma unroll
    for (int r = 0; r < 8; r++)
#pragma unroll
        for (int j = 0; j < 4; j++) acc[r][j] = 0ull;

    gemm_128(As, Bs, tr, tc, acc);

    float bias[4];
#pragma unroll
    for (int j = 0; j < 4; j++) bias[j] = Qb[tc + 32 * j];

    const int rbase = row0 + tr * 8;
#pragma unroll
    for (int r = 0; r < 8; r++) {
        float* o = g_H + (size_t)(rbase + r) * HH + tc;
#pragma unroll
        for (int j = 0; j < 4; j++) {
            float lo, hi;
            unpack2(acc[r][j], lo, hi);
            o[32 * j] = leaky(lo + hi + bias[j]);
        }
    }
}

// ---------------------------------------------------------------------------
// K2: wsh[b,n,h] = sum_k H[b,js[k],h]*ws[k] / (sum_k ws + eps)
// ---------------------------------------------------------------------------
__global__ void __launch_bounds__(128) k2_gather(const float* __restrict__ weights,
                                                 const int* __restrict__ ns) {
    const int n = blockIdx.x;
    const int t = threadIdx.x;
    const int c4 = t & 31;
    const int kg = t >> 5;

    __shared__ float ws[KK];
    __shared__ int   js[KK];
    __shared__ float wsum_s;
    __shared__ float4 red0[4][32];
    __shared__ float4 red1[4][32];

    if (t < KK) {
        int j = ns[n * KK + t];
        js[t] = j;
        float w = weights[(size_t)n * NN + j];
        ws[t] = w;
#pragma unroll
        for (int off = 16; off; off >>= 1)
            w += __shfl_xor_sync(0xffffffffu, w, off);
        if (t == 0) wsum_s = w;
    }
    __syncthreads();

    const float* H0 = g_H;
    const float* H1 = g_H + (size_t)NN * HH;
    float4 a0 = make_float4(0.f, 0.f, 0.f, 0.f);
    float4 a1 = make_float4(0.f, 0.f, 0.f, 0.f);
#pragma unroll
    for (int k = kg; k < KK; k += 4) {
        const int j = js[k];
        const float w = ws[k];
        const float4 h0 = *(const float4*)&H0[(size_t)j * HH + 4 * c4];
        const float4 h1 = *(const float4*)&H1[(size_t)j * HH + 4 * c4];
        a0.x = fmaf(h0.x, w, a0.x); a0.y = fmaf(h0.y, w, a0.y);
        a0.z = fmaf(h0.z, w, a0.z); a0.w = fmaf(h0.w, w, a0.w);
        a1.x = fmaf(h1.x, w, a1.x); a1.y = fmaf(h1.y, w, a1.y);
        a1.z = fmaf(h1.z, w, a1.z); a1.w = fmaf(h1.w, w, a1.w);
    }
    red0[kg][c4] = a0;
    red1[kg][c4] = a1;
    __syncthreads();

    if (t < 64) {
        const int b = t >> 5;
        const int c = t & 31;
        const float4 p0 = b ? red1[0][c] : red0[0][c];
        const float4 p1 = b ? red1[1][c] : red0[1][c];
        const float4 p2 = b ? red1[2][c] : red0[2][c];
        const float4 p3 = b ? red1[3][c] : red0[3][c];
        const float inv = 1.f / (wsum_s + EPS);
        float4 o;
        o.x = (p0.x + p1.x + p2.x + p3.x) * inv;
        o.y = (p0.y + p1.y + p2.y + p3.y) * inv;
        o.z = (p0.z + p1.z + p2.z + p3.z) * inv;
        o.w = (p0.w + p1.w + p2.w + p3.w) * inv;
        *(float4*)&g_wsh[((size_t)b * NN + n) * HH + 4 * c] = o;
    }
}

// ---------------------------------------------------------------------------
// K3: out = normalize(leaky([emb | wsh] @ Ww + Wb)), two K=128 stages
// ---------------------------------------------------------------------------
__global__ void __launch_bounds__(256) k3_out(const float* __restrict__ emb,
                                              const float* __restrict__ Ww,
                                              const float* __restrict__ Wb,
                                              float* __restrict__ out) {
    extern __shared__ float sm[];
    float* As = sm;
    float* Bs = sm + AS_FLOATS;
    const int t = threadIdx.x;
    const int tr = t >> 5, tc = t & 31;
    const int row0 = blockIdx.x * RT;

    ull acc[8][4];
#pragma unroll
    for (int r = 0; r < 8; r++)
#pragma unroll
        for (int j = 0; j < 4; j++) acc[r][j] = 0ull;

    // stage 0: A = emb rows, B = Ww[0:128,:]
    stage_A(As, emb + (size_t)row0 * CC, t);
    stage_BT(Bs, Ww, t);
    __syncthreads();
    gemm_128(As, Bs, tr, tc, acc);
    __syncthreads();

    // stage 1: A = wsh rows, B = Ww[128:256,:]
    stage_A(As, g_wsh + (size_t)row0 * HH, t);
    stage_BT(Bs, Ww + 128 * HH, t);
    __syncthreads();
    gemm_128(As, Bs, tr, tc, acc);

    float bias[4];
#pragma unroll
    for (int j = 0; j < 4; j++) bias[j] = Wb[tc + 32 * j];

    float v[8][4];
#pragma unroll
    for (int r = 0; r < 8; r++) {
        float s = 0.f;
#pragma unroll
        for (int j = 0; j < 4; j++) {
            float lo, hi;
            unpack2(acc[r][j], lo, hi);
            float x = leaky(lo + hi + bias[j]);
            v[r][j] = x;
            s = fmaf(x, x, s);
        }
        // full-warp reduce: warp covers all 32 tc for this tr -> row sum-sq
#pragma unroll
        for (int off = 16; off; off >>= 1)
            s += __shfl_xor_sync(0xffffffffu, s, off);
        const float inv = 1.f / (sqrtf(s) + EPS);
        float* o = out + (size_t)(row0 + tr * 8 + r) * HH + tc;
#pragma unroll
        for (int j = 0; j < 4; j++) o[32 * j] = v[r][j] * inv;
    }
}

// ---------------------------------------------------------------------------
extern "C" void kernel_launch(void* const* d_in, const int* in_sizes, int n_in,
                              void* d_out, int out_size) {
    const float* emb     = (const float*)d_in[0];  // (B, N, C)
    const float* weights = (const float*)d_in[1];  // (N, N)
    const int*   ns      = (const int*)  d_in[2];  // (N, K)
    const float* Qw      = (const float*)d_in[3];  // (C, H)
    const float* Qb      = (const float*)d_in[4];  // (H,)
    const float* Ww      = (const float*)d_in[5];  // (C+H, H)
    const float* Wb      = (const float*)d_in[6];  // (H,)
    float* out = (float*)d_out;                    // (B, N, H)

    (void)in_sizes; (void)n_in; (void)out_size;

    cudaFuncSetAttribute(k1_qgemm, cudaFuncAttributeMaxDynamicSharedMemorySize,
                         SMEM_BYTES);
    cudaFuncSetAttribute(k3_out, cudaFuncAttributeMaxDynamicSharedMemorySize,
                         SMEM_BYTES);

    k1_qgemm<<<(BB * NN) / RT, 256, SMEM_BYTES>>>(emb, Qw, Qb);
    k2_gather<<<NN, 128>>>(weights, ns);
    k3_out<<<(BB * NN) / RT, 256, SMEM_BYTES>>>(emb, Ww, Wb, out);
}

// round 10
// speedup vs baseline: 1.6143x; 1.6130x over previous
#include <cuda_runtime.h>
#include <math.h>
#include <stdint.h>

#define BB 2
#define NN 8192
#define KK 32
#define CC 128
#define HH 128
#define ALPHA 0.3f
#define EPS 1e-6f

#define RT 64                  // rows per block tile
#define AST 132                // As/Vs stride in 4B words (132%32==4 -> cf frags)
#define BSTW 132               // Bs stride in 4B words
#define AS_WORDS (RT * AST)    // 8448
#define BS_WORDS (128 * BSTW)  // 16896
#define SMEM_BYTES ((AS_WORDS + BS_WORDS) * 4)   // 101376 B -> 2 blocks/SM

__device__ float g_H[(size_t)BB * NN * HH];    // leaky(emb @ Qw + Qb), 8 MB
__device__ float g_wsh[(size_t)BB * NN * HH];  // weighted-sum hidden,  8 MB

__device__ __forceinline__ uint32_t to_tf32(float f) {
    uint32_t r;
    asm("cvt.rna.tf32.f32 %0, %1;" : "=r"(r) : "f"(f));
    return r;
}
__device__ __forceinline__ void mma_tf32(float c[4], uint32_t a0, uint32_t a1,
                                         uint32_t a2, uint32_t a3,
                                         uint32_t b0, uint32_t b1) {
    asm("mma.sync.aligned.m16n8k8.row.col.f32.tf32.tf32.f32 "
        "{%0,%1,%2,%3}, {%4,%5,%6,%7}, {%8,%9}, {%0,%1,%2,%3};"
        : "+f"(c[0]), "+f"(c[1]), "+f"(c[2]), "+f"(c[3])
        : "r"(a0), "r"(a1), "r"(a2), "r"(a3), "r"(b0), "r"(b1));
}
__device__ __forceinline__ float leaky(float v) {
    return (v >= 0.f) ? v : ALPHA * v;
}

// ---- stage A: 64 rows x 128 cols fp32 -> tf32 bits, stride AST ------------
__device__ __forceinline__ void stage_A(uint32_t* __restrict__ As,
                                        const float* __restrict__ src, int t) {
    const float4* s4 = (const float4*)src;
#pragma unroll
    for (int i = 0; i < 8; i++) {
        int id = t + i * 256;
        int row = id >> 5;
        int c = (id & 31) << 2;
        float4 v = s4[id];
        uint4 u = make_uint4(to_tf32(v.x), to_tf32(v.y), to_tf32(v.z), to_tf32(v.w));
        *(uint4*)&As[row * AST + c] = u;
    }
}
// ---- stage B: 128 x 128 weights fp32 -> tf32 bits, stride BSTW ------------
__device__ __forceinline__ void stage_B(uint32_t* __restrict__ Bs,
                                        const float* __restrict__ W, int t) {
    const float4* s4 = (const float4*)W;
#pragma unroll
    for (int i = 0; i < 16; i++) {
        int id = t + i * 256;
        int row = id >> 5;
        int c = (id & 31) << 2;
        float4 v = s4[id];
        uint4 u = make_uint4(to_tf32(v.x), to_tf32(v.y), to_tf32(v.z), to_tf32(v.w));
        *(uint4*)&Bs[row * BSTW + c] = u;
    }
}

// ---- tensor-core mainloop over K=128 --------------------------------------
// warp w owns cols n0=w*16 (2 n-tiles), all 64 rows (4 m-tiles of 16).
// c[mt][nt][4] accumulators per thread.
__device__ __forceinline__ void gemm_tc_128(const uint32_t* __restrict__ As,
                                            const uint32_t* __restrict__ Bs,
                                            int lane, int n0,
                                            float c[4][2][4]) {
    const uint32_t* Ab = As + (lane >> 2) * AST + (lane & 3);
    const uint32_t* Bb = Bs + (lane & 3) * BSTW + n0 + (lane >> 2);
#pragma unroll 4
    for (int ks = 0; ks < 16; ks++) {
        const int kb = ks * 8;
        uint32_t b00 = Bb[kb * BSTW];
        uint32_t b01 = Bb[kb * BSTW + 4 * BSTW];
        uint32_t b10 = Bb[kb * BSTW + 8];
        uint32_t b11 = Bb[kb * BSTW + 4 * BSTW + 8];
#pragma unroll
        for (int mt = 0; mt < 4; mt++) {
            const uint32_t* Am = Ab + mt * 16 * AST + kb;
            uint32_t a0 = Am[0];
            uint32_t a1 = Am[8 * AST];
            uint32_t a2 = Am[4];
            uint32_t a3 = Am[8 * AST + 4];
            mma_tf32(c[mt][0], a0, a1, a2, a3, b00, b01);
            mma_tf32(c[mt][1], a0, a1, a2, a3, b10, b11);
        }
    }
}

// ---------------------------------------------------------------------------
// K1: H[row,h] = leaky(emb[row,:] @ Qw + Qb)   (tf32 tensor cores)
// ---------------------------------------------------------------------------
__global__ void __launch_bounds__(256) k1_qgemm(const float* __restrict__ emb,
                                                const float* __restrict__ Qw,
                                                const float* __restrict__ Qb) {
    extern __shared__ uint32_t sm[];
    uint32_t* As = sm;
    uint32_t* Bs = sm + AS_WORDS;
    const int t = threadIdx.x;
    const int lane = t & 31;
    const int n0 = (t >> 5) * 16;
    const int row0 = blockIdx.x * RT;

    stage_A(As, emb + (size_t)row0 * CC, t);
    stage_B(Bs, Qw, t);
    __syncthreads();

    float c[4][2][4];
#pragma unroll
    for (int mt = 0; mt < 4; mt++)
#pragma unroll
        for (int nt = 0; nt < 2; nt++)
#pragma unroll
            for (int i = 0; i < 4; i++) c[mt][nt][i] = 0.f;

    gemm_tc_128(As, Bs, lane, n0, c);

#pragma unroll
    for (int nt = 0; nt < 2; nt++) {
        const int col = n0 + nt * 8 + 2 * (lane & 3);
        const float2 bias = *(const float2*)(Qb + col);
#pragma unroll
        for (int mt = 0; mt < 4; mt++) {
            const int r0 = row0 + mt * 16 + (lane >> 2);
            float2 v0 = make_float2(leaky(c[mt][nt][0] + bias.x),
                                    leaky(c[mt][nt][1] + bias.y));
            float2 v1 = make_float2(leaky(c[mt][nt][2] + bias.x),
                                    leaky(c[mt][nt][3] + bias.y));
            *(float2*)&g_H[(size_t)r0 * HH + col] = v0;
            *(float2*)&g_H[(size_t)(r0 + 8) * HH + col] = v1;
        }
    }
}

// ---------------------------------------------------------------------------
// K2: wsh[b,n,h] = sum_k H[b,js[k],h]*ws[k] / (sum_k ws + eps)  (fp32)
// ---------------------------------------------------------------------------
__global__ void __launch_bounds__(128) k2_gather(const float* __restrict__ weights,
                                                 const int* __restrict__ ns) {
    const int n = blockIdx.x;
    const int t = threadIdx.x;
    const int c4 = t & 31;
    const int kg = t >> 5;

    __shared__ float ws[KK];
    __shared__ int   js[KK];
    __shared__ float wsum_s;
    __shared__ float4 red0[4][32];
    __shared__ float4 red1[4][32];

    if (t < KK) {
        int j = ns[n * KK + t];
        js[t] = j;
        float w = weights[(size_t)n * NN + j];
        ws[t] = w;
#pragma unroll
        for (int off = 16; off; off >>= 1)
            w += __shfl_xor_sync(0xffffffffu, w, off);
        if (t == 0) wsum_s = w;
    }
    __syncthreads();

    const float* H0 = g_H;
    const float* H1 = g_H + (size_t)NN * HH;
    float4 a0 = make_float4(0.f, 0.f, 0.f, 0.f);
    float4 a1 = make_float4(0.f, 0.f, 0.f, 0.f);
#pragma unroll
    for (int k = kg; k < KK; k += 4) {
        const int j = js[k];
        const float w = ws[k];
        const float4 h0 = *(const float4*)&H0[(size_t)j * HH + 4 * c4];
        const float4 h1 = *(const float4*)&H1[(size_t)j * HH + 4 * c4];
        a0.x = fmaf(h0.x, w, a0.x); a0.y = fmaf(h0.y, w, a0.y);
        a0.z = fmaf(h0.z, w, a0.z); a0.w = fmaf(h0.w, w, a0.w);
        a1.x = fmaf(h1.x, w, a1.x); a1.y = fmaf(h1.y, w, a1.y);
        a1.z = fmaf(h1.z, w, a1.z); a1.w = fmaf(h1.w, w, a1.w);
    }
    red0[kg][c4] = a0;
    red1[kg][c4] = a1;
    __syncthreads();

    if (t < 64) {
        const int b = t >> 5;
        const int c = t & 31;
        const float4 p0 = b ? red1[0][c] : red0[0][c];
        const float4 p1 = b ? red1[1][c] : red0[1][c];
        const float4 p2 = b ? red1[2][c] : red0[2][c];
        const float4 p3 = b ? red1[3][c] : red0[3][c];
        const float inv = 1.f / (wsum_s + EPS);
        float4 o;
        o.x = (p0.x + p1.x + p2.x + p3.x) * inv;
        o.y = (p0.y + p1.y + p2.y + p3.y) * inv;
        o.z = (p0.z + p1.z + p2.z + p3.z) * inv;
        o.w = (p0.w + p1.w + p2.w + p3.w) * inv;
        *(float4*)&g_wsh[((size_t)b * NN + n) * HH + 4 * c] = o;
    }
}

// ---------------------------------------------------------------------------
// K3: out = normalize(leaky([emb | wsh] @ Ww + Wb)), two tf32 K=128 stages
// ---------------------------------------------------------------------------
__global__ void __launch_bounds__(256) k3_out(const float* __restrict__ emb,
                                              const float* __restrict__ Ww,
                                              const float* __restrict__ Wb,
                                              float* __restrict__ out) {
    extern __shared__ uint32_t sm[];
    uint32_t* As = sm;
    uint32_t* Bs = sm + AS_WORDS;
    const int t = threadIdx.x;
    const int lane = t & 31;
    const int n0 = (t >> 5) * 16;
    const int row0 = blockIdx.x * RT;

    float c[4][2][4];
#pragma unroll
    for (int mt = 0; mt < 4; mt++)
#pragma unroll
        for (int nt = 0; nt < 2; nt++)
#pragma unroll
            for (int i = 0; i < 4; i++) c[mt][nt][i] = 0.f;

    // stage 0: A = emb rows, B = Ww[0:128,:]
    stage_A(As, emb + (size_t)row0 * CC, t);
    stage_B(Bs, Ww, t);
    __syncthreads();
    gemm_tc_128(As, Bs, lane, n0, c);
    __syncthreads();

    // stage 1: A = wsh rows, B = Ww[128:256,:]
    stage_A(As, g_wsh + (size_t)row0 * HH, t);
    stage_B(Bs, Ww + 128 * HH, t);
    __syncthreads();
    gemm_tc_128(As, Bs, lane, n0, c);
    __syncthreads();   // all warps done reading As before reuse as Vs

    // epilogue: bias + leaky into Vs, then row-norm and store
    float* Vs = (float*)As;   // 64 x AST
#pragma unroll
    for (int nt = 0; nt < 2; nt++) {
        const int col = n0 + nt * 8 + 2 * (lane & 3);
        const float2 bias = *(const float2*)(Wb + col);
#pragma unroll
        for (int mt = 0; mt < 4; mt++) {
            const int r = mt * 16 + (lane >> 2);
            *(float2*)&Vs[r * AST + col] =
                make_float2(leaky(c[mt][nt][0] + bias.x),
                            leaky(c[mt][nt][1] + bias.y));
            *(float2*)&Vs[(r + 8) * AST + col] =
                make_float2(leaky(c[mt][nt][2] + bias.x),
                            leaky(c[mt][nt][3] + bias.y));
        }
    }
    __syncthreads();

    // 4 threads per row, 32 cols each
    const int row = t >> 2;
    const int q = t & 3;
    float4 vv[8];
    float ssq = 0.f;
#pragma unroll
    for (int i = 0; i < 8; i++) {
        vv[i] = *(const float4*)&Vs[row * AST + q * 32 + i * 4];
        ssq = fmaf(vv[i].x, vv[i].x, ssq);
        ssq = fmaf(vv[i].y, vv[i].y, ssq);
        ssq = fmaf(vv[i].z, vv[i].z, ssq);
        ssq = fmaf(vv[i].w, vv[i].w, ssq);
    }
    ssq += __shfl_xor_sync(0xffffffffu, ssq, 1);
    ssq += __shfl_xor_sync(0xffffffffu, ssq, 2);
    const float inv = 1.f / (sqrtf(ssq) + EPS);
    float* o = out + (size_t)(row0 + row) * HH + q * 32;
#pragma unroll
    for (int i = 0; i < 8; i++) {
        *(float4*)(o + i * 4) = make_float4(vv[i].x * inv, vv[i].y * inv,
                                            vv[i].z * inv, vv[i].w * inv);
    }
}

// ---------------------------------------------------------------------------
extern "C" void kernel_launch(void* const* d_in, const int* in_sizes, int n_in,
                              void* d_out, int out_size) {
    const float* emb     = (const float*)d_in[0];  // (B, N, C)
    const float* weights = (const float*)d_in[1];  // (N, N)
    const int*   ns      = (const int*)  d_in[2];  // (N, K)
    const float* Qw      = (const float*)d_in[3];  // (C, H)
    const float* Qb      = (const float*)d_in[4];  // (H,)
    const float* Ww      = (const float*)d_in[5];  // (C+H, H)
    const float* Wb      = (const float*)d_in[6];  // (H,)
    float* out = (float*)d_out;                    // (B, N, H)

    (void)in_sizes; (void)n_in; (void)out_size;

    cudaFuncSetAttribute(k1_qgemm, cudaFuncAttributeMaxDynamicSharedMemorySize,
                         SMEM_BYTES);
    cudaFuncSetAttribute(k3_out, cudaFuncAttributeMaxDynamicSharedMemorySize,
                         SMEM_BYTES);

    k1_qgemm<<<(BB * NN) / RT, 256, SMEM_BYTES>>>(emb, Qw, Qb);
    k2_gather<<<NN, 128>>>(weights, ns);
    k3_out<<<(BB * NN) / RT, 256, SMEM_BYTES>>>(emb, Ww, Wb, out);
}